// round 4
// baseline (speedup 1.0000x reference)
#include <cuda_runtime.h>

// ---------------------------------------------------------------------------
// QHashSoftmax: LUT fixed-point softmax, exact-integer reformulation.
//   idx = clamp(rne(x*16), -128, 127) & 255            (cvt.rni.sat.s8)
//   k[idx] = clip(rint(exp(signed(idx)/16 * scale)*128), 0, 127)   (u8 LUT)
//   S = sum(k) over 1024-element row   (exact integer, < 2^18)
//   t = min(floor(S/k), 1023)   (k=0 -> 1023)  [fp32 div+floor exact here]
//   out = min(rint(128/t), 127) / 128           (t=0 -> inf -> 127)
//
// Layout:
//  - exp table u8[256] = 64 smem words  -> gather conflict degree <= 2
//  - out table indexed by k: u8[128] = 32 words, one/bank -> conflict-FREE
//  - 8 rows/block, state byte-packed (pidx/pk u32 per float4), dp4a row sums
//  - 3 barriers per 8 rows; streaming ld/st (.cs) keeps L1 for the gathers
// ---------------------------------------------------------------------------

__device__ unsigned char g_exp_u8[256];   // indexed by wrapped code (q & 255)

__global__ void qhs_setup_kernel(const float* __restrict__ scale_ptr) {
    int i = threadIdx.x;                      // 0..255 = wrapped address
    float scale = *scale_ptr;
    int sv = (i >= 128) ? (i - 256) : i;      // two's-complement decode
    float val = (float)sv * 0.0625f * scale;  // fp32, matches reference
    double e = exp((double)val);              // high-precision exp
    double r = rint(e * 128.0);               // round half to even
    if (r > 127.0) r = 127.0;
    if (r < 0.0)   r = 0.0;
    g_exp_u8[i] = (unsigned char)(int)r;
}

// clamp(round-half-even(f), -128, 127) & 255 in one convert + one mask
__device__ __forceinline__ unsigned qhs_code(float f) {
    int r;
    asm("cvt.rni.sat.s8.f32 %0, %1;" : "=r"(r) : "f"(f));
    return (unsigned)r & 255u;
}

#define ROWS_PER_BLOCK 8

__global__ __launch_bounds__(256) void qhs_main_kernel(
    const float4* __restrict__ x, float4* __restrict__ out)
{
    __shared__ unsigned char sk8[256];                    // exp codes (u8)
    __shared__ unsigned char ocode[ROWS_PER_BLOCK][128];  // out codes by k
    __shared__ int sS[ROWS_PER_BLOCK];                    // row sums

    const int tid = threadIdx.x;

    sk8[tid] = g_exp_u8[tid];
    if (tid < ROWS_PER_BLOCK) sS[tid] = 0;

    const long long base =
        (long long)blockIdx.x * (ROWS_PER_BLOCK * 256) + tid;

    // ---- Load + quantize to packed codes (no table needed yet) ----------
    unsigned pidx[ROWS_PER_BLOCK];
#pragma unroll
    for (int r = 0; r < ROWS_PER_BLOCK; r++) {
        float4 v = __ldcs(&x[base + r * 256]);
        unsigned c0 = qhs_code(v.x * 16.0f);
        unsigned c1 = qhs_code(v.y * 16.0f);
        unsigned c2 = qhs_code(v.z * 16.0f);
        unsigned c3 = qhs_code(v.w * 16.0f);
        pidx[r] = c0 | (c1 << 8) | (c2 << 16) | (c3 << 24);
    }

    __syncthreads();   // sk8 + sS ready

    // ---- Phase 1: gather k bytes, pack, dp4a row sums -------------------
    unsigned pk[ROWS_PER_BLOCK];
#pragma unroll
    for (int r = 0; r < ROWS_PER_BLOCK; r++) {
        unsigned p = pidx[r];
        unsigned k0 = sk8[p & 255u];
        unsigned k1 = sk8[(p >> 8) & 255u];
        unsigned k2 = sk8[(p >> 16) & 255u];
        unsigned k3 = sk8[p >> 24];
        pk[r] = k0 | (k1 << 8) | (k2 << 16) | (k3 << 24);
        int s = __dp4a(pk[r], 0x01010101u, 0u);
        s = __reduce_add_sync(0xFFFFFFFFu, s);
        if ((tid & 31) == 0) atomicAdd(&sS[r], s);
    }

    __syncthreads();   // all sums complete

    // ---- Phase 2: per-row output-code tables (indexed by k) -------------
    // 8 rows x 128 entries = 1024; each thread builds 4.
#pragma unroll
    for (int e = tid; e < ROWS_PER_BLOCK * 128; e += 256) {
        int row = e >> 7;
        int kk  = e & 127;
        float Sf = (float)sS[row];                     // exact (< 2^18)
        // floor(S/k): IEEE div then floor — exact (err 0.0078/k < 1/k gap).
        // kk==0 -> +inf -> clipped to 1023 (reference e==0 branch).
        float t = fminf(floorf(__fdiv_rn(Sf, (float)kk)), 1023.0f);
        // t==0 -> +inf -> clipped to 127 (reference 1/0 saturation).
        float code = fminf(rintf(__fdiv_rn(128.0f, t)), 127.0f);
        ocode[row][kk] = (unsigned char)(int)code;
    }

    __syncthreads();   // tables ready

    // ---- Phase 3: conflict-free byte gathers + streaming stores ---------
#pragma unroll
    for (int r = 0; r < ROWS_PER_BLOCK; r++) {
        unsigned p = pk[r];
        float4 o;
        o.x = (float)ocode[r][p & 255u]         * 0.0078125f;
        o.y = (float)ocode[r][(p >> 8) & 255u]  * 0.0078125f;
        o.z = (float)ocode[r][(p >> 16) & 255u] * 0.0078125f;
        o.w = (float)ocode[r][p >> 24]          * 0.0078125f;
        __stcs(&out[base + r * 256], o);
    }
}

extern "C" void kernel_launch(void* const* d_in, const int* in_sizes, int n_in,
                              void* d_out, int out_size) {
    const float* x     = (const float*)d_in[0];   // [4,12,1024,1024] fp32
    const float* scale = (const float*)d_in[1];   // scalar fp32

    const int n_elems = in_sizes[0];
    const int n_rows  = n_elems >> 10;                   // rows of 1024
    const int n_blocks = n_rows / ROWS_PER_BLOCK;

    qhs_setup_kernel<<<1, 256>>>(scale);
    qhs_main_kernel<<<n_blocks, 256>>>((const float4*)x, (float4*)d_out);
}